// round 15
// baseline (speedup 1.0000x reference)
#include <cuda_runtime.h>

// WeightedAggregator: out[b,:] = sum_k (w[b,k]/sum_j w[b,j]) * features[idx[b,k],:]
// B = 50000, K = 16, D = 128 (fp32). neigh_idx is int32 (JAX demotes int64).
//
// R15: persistent 4-phase index-windowed gather with SMEM-resident partials.
// R12 proved phase windowing pushes feature DRAM reads to the compulsory
// unique-row floor (~204 MB vs 297 MB), but its gmem partial round trips
// leaked ~120 MB. Here each warp owns ROWS_PW=10 output rows whose partial
// sums live in shared memory across all 4 phases; chip-wide phase coherence
// comes from bounded-spin grid barriers (monotonic-ticket, replay-safe,
// deadlock-impossible). Host verifies one-wave co-residency via the
// occupancy API and falls back to the proven flat kernel otherwise.

#define K_NEIGH 16
#define FEAT_D 128
#define ROWS_PW 10
#define WARPS_CTA 4
#define N_PHASES 4

__device__ unsigned g_bar[N_PHASES - 1];   // zero-initialized

// Bounded-spin grid barrier. Monotonic ticket scheme: works across graph
// replays without reset; bounded spin guarantees forward progress even if
// co-residency assumptions break (then it is merely a perf no-op).
__device__ __forceinline__ void soft_grid_barrier(int b, unsigned grid) {
    __syncthreads();
    if (threadIdx.x == 0) {
        const unsigned ticket = atomicAdd(&g_bar[b], 1u);
        const unsigned target = (ticket / grid + 1u) * grid;
        unsigned spins = 0;
        while (*(volatile unsigned*)&g_bar[b] < target && spins < (1u << 26))
            spins++;
    }
    __syncthreads();
}

// Gather the window [lo,hi) contribution of one output row into two chains.
__device__ __forceinline__ void gather_window(
    const float4* __restrict__ feat4, int lane, float w, int ix,
    int lo, int hi, float4& a0, float4& a1)
{
    #pragma unroll
    for (int k = 0; k < K_NEIGH; k += 2) {
        const int   i0 = __shfl_sync(0xffffffffu, ix, k);
        const int   i1 = __shfl_sync(0xffffffffu, ix, k + 1);
        const float w0 = __shfl_sync(0xffffffffu, w, k);
        const float w1 = __shfl_sync(0xffffffffu, w, k + 1);
        if (i0 >= lo && i0 < hi) {
            const float4 f = __ldg(feat4 + (long long)i0 * (FEAT_D / 4) + lane);
            a0.x += w0 * f.x;  a0.y += w0 * f.y;
            a0.z += w0 * f.z;  a0.w += w0 * f.w;
        }
        if (i1 >= lo && i1 < hi) {
            const float4 f = __ldg(feat4 + (long long)i1 * (FEAT_D / 4) + lane);
            a1.x += w1 * f.x;  a1.y += w1 * f.y;
            a1.z += w1 * f.z;  a1.w += w1 * f.w;
        }
    }
}

__global__ __launch_bounds__(32 * WARPS_CTA)
void weighted_agg_persistent(const float* __restrict__ features,
                             const float* __restrict__ neigh_w,
                             const int* __restrict__ neigh_idx,
                             float* __restrict__ out,
                             int B, int N)
{
    __shared__ float4 part[WARPS_CTA][ROWS_PW][32];   // 20 KB

    const int lane   = threadIdx.x & 31;
    const int wid    = threadIdx.x >> 5;
    const int gwarp  = blockIdx.x * WARPS_CTA + wid;
    const int base   = gwarp * ROWS_PW;               // first owned row
    const int q      = N / N_PHASES;

    const float4* __restrict__ feat4 = (const float4*)features;

    #pragma unroll
    for (int phase = 0; phase < N_PHASES; phase++) {
        const int lo = phase * q;
        const int hi = (phase == N_PHASES - 1) ? N : lo + q;

        for (int rw = 0; rw < ROWS_PW; rw++) {
            const int row = base + rw;
            if (row >= B) break;                      // warp-uniform

            float w  = 0.0f;
            int   ix = 0;
            if (lane < K_NEIGH) {
                w  = neigh_w  [row * K_NEIGH + lane];
                ix = neigh_idx[row * K_NEIGH + lane];
            }

            float4 a0 = make_float4(0.f, 0.f, 0.f, 0.f);
            float4 a1 = make_float4(0.f, 0.f, 0.f, 0.f);
            gather_window(feat4, lane, w, ix, lo, hi, a0, a1);

            float4 c;
            c.x = a0.x + a1.x;  c.y = a0.y + a1.y;
            c.z = a0.z + a1.z;  c.w = a0.w + a1.w;

            if (phase == 0) {
                part[wid][rw][lane] = c;              // initialize
            } else if (phase < N_PHASES - 1) {
                float4 p = part[wid][rw][lane];
                p.x += c.x;  p.y += c.y;  p.z += c.z;  p.w += c.w;
                part[wid][rw][lane] = p;
            } else {
                // Final phase: combine, normalize, write out.
                float s = w;
                #pragma unroll
                for (int off = 16; off > 0; off >>= 1)
                    s += __shfl_xor_sync(0xffffffffu, s, off);
                const float inv = 1.0f / s;

                float4 p = part[wid][rw][lane];
                float4 r;
                r.x = (p.x + c.x) * inv;
                r.y = (p.y + c.y) * inv;
                r.z = (p.z + c.z) * inv;
                r.w = (p.w + c.w) * inv;
                ((float4*)out)[(long long)row * (FEAT_D / 4) + lane] = r;
            }
        }

        if (phase < N_PHASES - 1)
            soft_grid_barrier(phase, gridDim.x);
    }
}

// Fallback: the proven flat kernel (52.6us ncu), used when one-wave
// co-residency cannot be guaranteed on the running device.
__global__ __launch_bounds__(128)
void weighted_agg_flat(const float* __restrict__ features,
                       const float* __restrict__ neigh_w,
                       const int* __restrict__ neigh_idx,
                       float* __restrict__ out,
                       int B)
{
    const int gtid = blockIdx.x * blockDim.x + threadIdx.x;
    const int row  = gtid >> 5;
    const int lane = threadIdx.x & 31;
    if (row >= B) return;

    float w  = 0.0f;
    int   ix = 0;
    if (lane < K_NEIGH) {
        w  = neigh_w  [row * K_NEIGH + lane];
        ix = neigh_idx[row * K_NEIGH + lane];
    }

    float s = w;
    #pragma unroll
    for (int off = 16; off > 0; off >>= 1)
        s += __shfl_xor_sync(0xffffffffu, s, off);
    const float inv = 1.0f / s;

    const float4* __restrict__ feat4 = (const float4*)features;

    float4 f[K_NEIGH];
    #pragma unroll
    for (int k = 0; k < K_NEIGH; k++) {
        const int ik = __shfl_sync(0xffffffffu, ix, k);
        f[k] = __ldg(feat4 + (long long)ik * (FEAT_D / 4) + lane);
    }

    float4 a0 = make_float4(0.f, 0.f, 0.f, 0.f);
    float4 a1 = make_float4(0.f, 0.f, 0.f, 0.f);
    #pragma unroll
    for (int k = 0; k < K_NEIGH; k += 2) {
        const float w0 = __shfl_sync(0xffffffffu, w, k);
        const float w1 = __shfl_sync(0xffffffffu, w, k + 1);
        a0.x += w0 * f[k].x;     a1.x += w1 * f[k + 1].x;
        a0.y += w0 * f[k].y;     a1.y += w1 * f[k + 1].y;
        a0.z += w0 * f[k].z;     a1.z += w1 * f[k + 1].z;
        a0.w += w0 * f[k].w;     a1.w += w1 * f[k + 1].w;
    }

    float4 r;
    r.x = (a0.x + a1.x) * inv;
    r.y = (a0.y + a1.y) * inv;
    r.z = (a0.z + a1.z) * inv;
    r.w = (a0.w + a1.w) * inv;

    ((float4*)out)[(long long)row * (FEAT_D / 4) + lane] = r;
}

extern "C" void kernel_launch(void* const* d_in, const int* in_sizes, int n_in,
                              void* d_out, int out_size)
{
    const float* features  = (const float*)d_in[0];   // [N_NODES, 128] fp32
    const float* neigh_w   = (const float*)d_in[1];   // [B, 16] fp32
    const int*   neigh_idx = (const int*)d_in[2];     // [B, 16] int32
    float*       out       = (float*)d_out;           // [B, 128] fp32

    const int B = in_sizes[1] / K_NEIGH;   // 50000
    const int N = in_sizes[0] / FEAT_D;    // 500000

    const int threads = 32 * WARPS_CTA;    // 128
    const int rows_per_cta = WARPS_CTA * ROWS_PW;                  // 40
    const int grid_needed  = (B + rows_per_cta - 1) / rows_per_cta; // 1250

    // One-wave co-residency check (host-only queries; graph-capture safe).
    int dev = 0, sms = 0, occ = 0;
    cudaGetDevice(&dev);
    cudaDeviceGetAttribute(&sms, cudaDevAttrMultiProcessorCount, dev);
    cudaOccupancyMaxActiveBlocksPerMultiprocessor(
        &occ, weighted_agg_persistent, threads, 0);

    if ((long long)occ * sms >= grid_needed) {
        weighted_agg_persistent<<<grid_needed, threads>>>(
            features, neigh_w, neigh_idx, out, B, N);
    } else {
        const int blocks = (B * 32 + threads - 1) / threads;
        weighted_agg_flat<<<blocks, threads>>>(features, neigh_w, neigh_idx, out, B);
    }
}